// round 14
// baseline (speedup 1.0000x reference)
#include <cuda_runtime.h>

typedef unsigned long long u64;
#define FUSED_N 34603008  // 8*66*256*256

// ---------------- scratch (device globals; no allocations) ----------------
__device__ float g_xg[8*24*256*256];   // unique gauss channels
__device__ float g_out1[8*256*256];    // dynamic-conv output
__device__ float g_pool1p[8*128*9*2];  // pooled predictor stage 1 (2 half-partials)
__device__ u64   g_kern2[8*1323];      // predicted kernels, (w,w) pairs
__device__ float g_treff[66*9];
__device__ float g_fug[66*24*9];       // scalar (for ring)
__device__ u64   g_fug2[66*24*9];      // (w,w) pairs
__device__ float g_W5[66*25];
__device__ u64   g_W52[66*25];
__device__ float g_cbias[66];
__device__ int   g_bby[24*4];          // per-u: ky0, ky1, kxe(mult of 4), NJ
__device__ u64   g_wg2[24*441];        // gauss bank (w,w) pairs per unique u
__device__ u64   g_p1w2[128*363];      // p1 weights (w,w) pairs

__device__ __forceinline__ float leaky(float v){ return v>0.f ? v : 0.2f*v; }
__device__ __forceinline__ u64 pk2(float lo, float hi){
  u64 r; asm("mov.b64 %0, {%1,%2};" : "=l"(r) : "f"(lo), "f"(hi)); return r;
}
__device__ __forceinline__ void up2(u64 v, float&a, float&b){
  asm("mov.b64 {%0,%1}, %2;" : "=f"(a), "=f"(b) : "l"(v));
}
__device__ __forceinline__ void fma2(u64&d, u64 a, u64 b){
  asm("fma.rn.f32x2 %0, %1, %2, %0;" : "+l"(d) : "l"(a), "l"(b));
}

// ---------------- kernel 0: precompute effective weights (+ pair packing) ----------------
__global__ void k_pre(const float* __restrict__ tr_w, const float* __restrict__ tr_b,
                      const float* __restrict__ fu_w, const float* __restrict__ fu_b,
                      const float* __restrict__ w_gauss, const float* __restrict__ p1_w){
  __shared__ float s_tr[66*9];
  int t = threadIdx.x;
  for(int i=t;i<66*9;i+=blockDim.x){
    int m=i/9, tap=i%9;
    s_tr[i] = tr_w[(m*3+0)*9+tap]+tr_w[(m*3+1)*9+tap]+tr_w[(m*3+2)*9+tap];
  }
  __syncthreads();
  int blk = blockIdx.x;
  if(blk<66){
    int o=blk;
    if(t<9) g_treff[o*9+t]=s_tr[o*9+t];
    for(int i=t;i<24*9;i+=blockDim.x){
      int u=i/9, tap=i%9;
      float s=0.f;
      for(int c=0;c<66;c++) if(c/22 + c/3 == u) s += fu_w[(o*132+c)*9+tap];
      g_fug[(o*24+u)*9+tap]=s;
      g_fug2[(o*24+u)*9+tap]=pk2(s,s);
    }
    for(int i=t;i<25;i+=blockDim.x){
      int p=i/5,q=i%5;
      float s=0.f;
      for(int m=0;m<66;m++)
        for(int dy=0;dy<3;dy++){
          int ey=p-dy; if(ey<0||ey>2) continue;
          for(int dx=0;dx<3;dx++){
            int ex=q-dx; if(ex<0||ex>2) continue;
            s += fu_w[(o*132+66+m)*9+dy*3+dx]*s_tr[m*9+ey*3+ex];
          }
        }
      g_W5[o*25+i]=s;
      g_W52[o*25+i]=pk2(s,s);
    }
    if(t==0){
      float s=fu_b[o];
      for(int m=0;m<66;m++){
        float ws=0.f;
        for(int tap=0;tap<9;tap++) ws+=fu_w[(o*132+66+m)*9+tap];
        s += tr_b[m]*ws;
      }
      g_cbias[o]=s;
    }
  } else if(blk<90){
    int u=blk-66;
    int k = u - u/8;
    const float* wk = w_gauss + 3*k*441;
    for(int i=t;i<441;i+=blockDim.x){ float v=wk[i]; g_wg2[u*441+i]=pk2(v,v); }
    if(t==0){
      int y0=21,y1=-1,x0c=21,x1c=-1;
      for(int i=0;i<441;i++) if(wk[i]!=0.f){
        int y=i/21, xx=i%21;
        if(y<y0)y0=y; if(y>y1)y1=y;
        if(xx<x0c)x0c=xx; if(xx>x1c)x1c=xx;
      }
      if(y1<0){y0=10;y1=10;x0c=10;x1c=10;}
      int kxe = x0c & ~3;
      int nj  = (x1c - kxe)/2 + 1;
      g_bby[u*4]=y0; g_bby[u*4+1]=y1; g_bby[u*4+2]=kxe; g_bby[u*4+3]=nj;
    }
  } else {
    int o=blk-90;  // 0..127
    for(int i=t;i<363;i+=blockDim.x){ float v=p1_w[o*363+i]; g_p1w2[o*363+i]=pk2(v,v); }
  }
}

// ---------------- gauss inner body (templated col-window) ----------------
template<int NJ>
__device__ __forceinline__ void gauss_body(const float* s_x, const u64* s_w2,
    int ky0, int ky1, int oy, int tx, int kxe,
    u64 (&accA)[2][4], u64 (&accB)[2][5]){
  const int IW=148;
  const int NL = (NJ+5)/2;
  #pragma unroll 1
  for(int r2=ky0;r2<=ky1+1;r2++){
    const ulonglong2* xr4=(const ulonglong2*)(s_x + (oy+r2)*IW + tx + kxe);
    u64 xp[NL*2];
    #pragma unroll
    for(int l=0;l<NL;l++){ ulonglong2 v=xr4[l]; xp[2*l]=v.x; xp[2*l+1]=v.y; }
    if(r2<=ky1){
      const ulonglong2* kr2=(const ulonglong2*)(s_w2 + r2*22 + kxe);
      #pragma unroll
      for(int j=0;j<NJ;j++){
        ulonglong2 wv=kr2[j];
        #pragma unroll
        for(int p=0;p<4;p++) fma2(accA[0][p], xp[p+j], wv.x);
        #pragma unroll
        for(int q=0;q<5;q++) fma2(accB[0][q], xp[q+j], wv.y);
      }
    }
    if(r2>ky0){
      const ulonglong2* kr2=(const ulonglong2*)(s_w2 + (r2-1)*22 + kxe);
      #pragma unroll
      for(int j=0;j<NJ;j++){
        ulonglong2 wv=kr2[j];
        #pragma unroll
        for(int p=0;p<4;p++) fma2(accA[1][p], xp[p+j], wv.x);
        #pragma unroll
        for(int q=0;q<5;q++) fma2(accB[1][q], xp[q+j], wv.y);
      }
    }
  }
}

// ---------------- mega1: p1pool(2304) + gauss(3072) + ax(2048) in one launch ----------------
__global__ __launch_bounds__(256,2) void k_mega1(const float* __restrict__ x,
    const float* __restrict__ p1_b, const float* __restrict__ cs_w,
    const float* __restrict__ cs_b, float* __restrict__ out){
  extern __shared__ float sm[];
  __shared__ float s_acc[8];
  int idx=blockIdx.x;
  int t=threadIdx.x;
  if(idx<2304){
    // ---------- p1pool ----------
    float* s_x = sm;                 // 14976 floats
    u64* s_w2 = (u64*)(sm + 14976);  // 3168 u64
    int bin=idx%9, yb=(idx/9)%32, b=idx/288;
    int chunk=yb>>1, half=yb&1;
    int bi=bin/3, bj=bin%3;
    int hs=bi*250/3, ws=bj*250/3;
    const int bh=84, bw=84;
    int r0=half*42;
    for(int i=t;i<14976;i+=256){
      int c=i/4992, r=i%4992, ly=r/96, lx=r%96;
      int gy=hs+r0-2+ly, gx=ws-2+lx;
      float v=0.f;
      if(gy>=0&&gy<256&&gx>=0&&gx<256) v=x[((b*3+c)*256+gy)*256+gx];
      s_x[i]=v;
    }
    int ch0=chunk*8;
    for(int i=t;i<3168;i+=256){
      int row=i/12, kx=i%12;
      int cc=row/33, rr=row%33, c=rr/11, ky=rr%11;
      s_w2[i] = (kx<11) ? g_p1w2[(ch0+cc)*363 + c*121 + ky*11 + kx] : 0ULL;
    }
    if(t<8) s_acc[t]=0.f;
    __syncthreads();
    for(int task=t;task<1176;task+=256){
      int cc=task/147, r=task%147, pr=r/7, sg=r%7;
      int oy=2*pr, ox0=sg*12;
      u64 accA[2][6], accB[2][7];
      #pragma unroll
      for(int w2=0;w2<2;w2++){
        #pragma unroll
        for(int j=0;j<6;j++) accA[w2][j]=0ULL;
        #pragma unroll
        for(int j=0;j<7;j++) accB[w2][j]=0ULL;
      }
      #pragma unroll 1
      for(int c=0;c<3;c++){
        const float* xb = s_x + c*4992;
        const u64* wbase = s_w2 + (cc*3+c)*11*12;
        #pragma unroll 1
        for(int r2=0;r2<12;r2++){
          const ulonglong2* xr4=(const ulonglong2*)(xb + (oy+r2)*96 + ox0);
          u64 xp[12];
          #pragma unroll
          for(int j=0;j<6;j++){ ulonglong2 v=xr4[j]; xp[2*j]=v.x; xp[2*j+1]=v.y; }
          if(r2<11){
            const ulonglong2* wr2=(const ulonglong2*)(wbase + r2*12);
            #pragma unroll
            for(int j=0;j<6;j++){
              ulonglong2 wv=wr2[j];
              #pragma unroll
              for(int p=0;p<6;p++) fma2(accA[0][p], xp[p+j], wv.x);
              if(j<5){
                #pragma unroll
                for(int q=0;q<7;q++) fma2(accB[0][q], xp[q+j], wv.y);
              }
            }
          }
          if(r2>0){
            const ulonglong2* wr2=(const ulonglong2*)(wbase + (r2-1)*12);
            #pragma unroll
            for(int j=0;j<6;j++){
              ulonglong2 wv=wr2[j];
              #pragma unroll
              for(int p=0;p<6;p++) fma2(accA[1][p], xp[p+j], wv.x);
              if(j<5){
                #pragma unroll
                for(int q=0;q<7;q++) fma2(accB[1][q], xp[q+j], wv.y);
              }
            }
          }
        }
      }
      float bias=p1_b[ch0+cc];
      float ls=0.f;
      #pragma unroll
      for(int w2=0;w2<2;w2++){
        #pragma unroll
        for(int p=0;p<6;p++){
          float alo,ahi,blo,bhi,nlo,nhi;
          up2(accA[w2][p],alo,ahi);
          up2(accB[w2][p],blo,bhi);
          up2(accB[w2][p+1],nlo,nhi);
          ls+=leaky(alo+bhi+bias);
          ls+=leaky(ahi+nlo+bias);
        }
      }
      atomicAdd(&s_acc[cc], ls);
    }
    __syncthreads();
    if(t<8) g_pool1p[((b*128+ch0+t)*9+bin)*2+half]=s_acc[t]/(float)(bh*bw);
  } else if(idx<5376){
    // ---------- gauss ----------
    int i2=idx-2304;
    int tile=i2&15, u=(i2>>4)%24, b=i2/384;
    float* s_x = sm;                     // 7712 floats
    u64* s_w2 = (u64*)(sm + 7712);       // 462 u64
    const int IW=148;
    int y0=(tile>>1)*32, x0=(tile&1)*128;
    int g = u/8;
    for(int i=t;i<462;i+=256){
      int row=i/22, kx=i%22;
      s_w2[i] = (kx<21) ? g_wg2[u*441+row*21+kx] : 0ULL;
    }
    for(int i=t;i<52*148;i+=256){
      int ly=i/IW, lx=i%IW;
      int gy=y0-10+ly, gx=x0-10+lx;
      float v=0.f;
      if(gy>=0&&gy<256&&gx>=0&&gx<256) v=x[((b*3+g)*256+gy)*256+gx];
      s_x[i]=v;
    }
    if(t<16) s_x[52*148+t]=0.f;
    __syncthreads();
    int ky0=g_bby[u*4], ky1=g_bby[u*4+1], kxe=g_bby[u*4+2], nj=g_bby[u*4+3];
    int pr=t>>4, tx=(t&15)*8;
    int oy=2*pr;
    u64 accA[2][4], accB[2][5];
    #pragma unroll
    for(int w2=0;w2<2;w2++){
      #pragma unroll
      for(int j=0;j<4;j++) accA[w2][j]=0ULL;
      #pragma unroll
      for(int j=0;j<5;j++) accB[w2][j]=0ULL;
    }
    switch(nj){
      case 1:  gauss_body<1> (s_x,s_w2,ky0,ky1,oy,tx,kxe,accA,accB); break;
      case 2:  gauss_body<2> (s_x,s_w2,ky0,ky1,oy,tx,kxe,accA,accB); break;
      case 3:  gauss_body<3> (s_x,s_w2,ky0,ky1,oy,tx,kxe,accA,accB); break;
      case 4:  gauss_body<4> (s_x,s_w2,ky0,ky1,oy,tx,kxe,accA,accB); break;
      case 5:  gauss_body<5> (s_x,s_w2,ky0,ky1,oy,tx,kxe,accA,accB); break;
      case 6:  gauss_body<6> (s_x,s_w2,ky0,ky1,oy,tx,kxe,accA,accB); break;
      case 7:  gauss_body<7> (s_x,s_w2,ky0,ky1,oy,tx,kxe,accA,accB); break;
      case 8:  gauss_body<8> (s_x,s_w2,ky0,ky1,oy,tx,kxe,accA,accB); break;
      case 9:  gauss_body<9> (s_x,s_w2,ky0,ky1,oy,tx,kxe,accA,accB); break;
      case 10: gauss_body<10>(s_x,s_w2,ky0,ky1,oy,tx,kxe,accA,accB); break;
      default: gauss_body<11>(s_x,s_w2,ky0,ky1,oy,tx,kxe,accA,accB); break;
    }
    #pragma unroll
    for(int w2=0;w2<2;w2++){
      int y=y0+oy+w2;
      float* op=&g_xg[((b*24+u)*256+y)*256+x0+tx];
      #pragma unroll
      for(int p=0;p<4;p++){
        float alo,ahi,blo,bhi,nlo,nhi;
        up2(accA[w2][p],alo,ahi); up2(accB[w2][p],blo,bhi); up2(accB[w2][p+1],nlo,nhi);
        op[2*p]=alo+bhi; op[2*p+1]=ahi+nlo;
      }
    }
  } else {
    // ---------- ax ----------
    int i3=idx-5376;
    int b=i3/256, xb=i3%256;
    int p=xb*256+t;
    int y=p/256, xx=p%256;
    float acc[3]={cs_b[0],cs_b[1],cs_b[2]};
    #pragma unroll
    for(int ic=0;ic<3;ic++){
      #pragma unroll
      for(int ky=0;ky<3;ky++){
        int gy=y+ky-1; if(gy<0||gy>255) continue;
        #pragma unroll
        for(int kx=0;kx<3;kx++){
          int gx=xx+kx-1; if(gx<0||gx>255) continue;
          float v=x[((b*3+ic)*256+gy)*256+gx];
          #pragma unroll
          for(int o=0;o<3;o++) acc[o]+=v*cs_w[(o*3+ic)*9+ky*3+kx];
        }
      }
    }
    #pragma unroll
    for(int o=0;o<3;o++) out[FUSED_N + ((b*3+o)*256+y)*256+xx]=acc[o];
  }
}

// ---------------- kernel 2: predictor tail ----------------
__global__ void k_pred(const float* __restrict__ p2_w, const float* __restrict__ p3_w){
  int b = blockIdx.x;
  int t = threadIdx.x; // 512
  __shared__ float s_h1[128*9];
  __shared__ float s_h3[441*3];
  __shared__ float s_h4[441*3];
  __shared__ float s_red[3];
  for(int i=t;i<1152;i+=512)
    s_h1[i]=g_pool1p[(b*1152+i)*2]+g_pool1p[(b*1152+i)*2+1];
  __syncthreads();
  for(int j=t;j<441;j+=512){
    float acc[9];
    #pragma unroll
    for(int s=0;s<9;s++) acc[s]=0.f;
    const float* wr = p2_w + j*128;
    for(int i=0;i<128;i++){
      float w=wr[i];
      #pragma unroll
      for(int s=0;s<9;s++) acc[s]+=w*s_h1[i*9+s];
    }
    #pragma unroll
    for(int s=0;s<9;s++) acc[s]=leaky(acc[s]);
    #pragma unroll
    for(int r2=0;r2<3;r2++)
      s_h3[j*3+r2] = (acc[r2*3]+acc[r2*3+1]+acc[r2*3+2])*(1.f/3.f);
  }
  __syncthreads();
  for(int q=t;q<441;q+=512){
    float a0=0,a1=0,a2=0;
    const float* wr = p3_w + q*441;
    for(int j=0;j<441;j++){
      float w=wr[j];
      a0+=w*s_h3[j*3+0]; a1+=w*s_h3[j*3+1]; a2+=w*s_h3[j*3+2];
    }
    s_h4[q*3+0]=a0; s_h4[q*3+1]=a1; s_h4[q*3+2]=a2;
  }
  __syncthreads();
  if(t<3){
    float mx=-1e30f;
    for(int q=0;q<441;q++) mx=fmaxf(mx, s_h4[q*3+t]);
    s_red[t]=mx;
  }
  __syncthreads();
  for(int i=t;i<1323;i+=512) s_h4[i]=expf(s_h4[i]-s_red[i%3]);
  __syncthreads();
  if(t<3){
    float sm2=0.f;
    for(int q=0;q<441;q++) sm2+=s_h4[q*3+t];
    s_red[t]=1.f/sm2;
  }
  __syncthreads();
  for(int i=t;i<1323;i+=512){
    float v=s_h4[i]*s_red[i%3];
    g_kern2[b*1323+i]=pk2(v,v);
  }
}

// ---------------- kernel 3: dynamic conv (f32x2, 2-row x 8px, 16x128 tiles, 128 thr) ----------------
__global__ __launch_bounds__(128) void k_dyn(const float* __restrict__ x){
  extern __shared__ float s_x[];    // 3*36*148 = 15984 floats
  __shared__ __align__(16) u64 s_k2[3*21*22];
  const int IW=148, CH=36*148;
  int tile=blockIdx.x, b=blockIdx.y;
  int y0=(tile>>1)*16, x0=(tile&1)*128;
  int t=threadIdx.x; // 128
  for(int i=t;i<1386;i+=128){
    int row=i/22, kx=i%22;
    s_k2[i] = (kx<21) ? g_kern2[b*1323+row*21+kx] : 0ULL;
  }
  for(int i=t;i<3*CH;i+=128){
    int c=i/CH, r=i%CH, ly=r/IW, lx=r%IW;
    int gy=y0-10+ly, gx=x0-10+lx;
    float v=0.f;
    if(gy>=0&&gy<256&&gx>=0&&gx<256) v=x[((b*3+c)*256+gy)*256+gx];
    s_x[i]=v;
  }
  __syncthreads();
  int pr=t>>4, tx=(t&15)*8;
  int oy=2*pr;
  u64 accA[2][4], accB[2][5];
  #pragma unroll
  for(int w2=0;w2<2;w2++){
    #pragma unroll
    for(int j=0;j<4;j++) accA[w2][j]=0ULL;
    #pragma unroll
    for(int j=0;j<5;j++) accB[w2][j]=0ULL;
  }
  #pragma unroll 1
  for(int c=0;c<3;c++){
    const float* xb = s_x + c*CH;
    const u64* kbase = s_k2 + c*21*22;
    #pragma unroll 1
    for(int r2=0;r2<22;r2++){
      const ulonglong2* xr4=(const ulonglong2*)(xb + (oy+r2)*IW + tx);
      u64 xp[14];
      #pragma unroll
      for(int j=0;j<7;j++){ ulonglong2 v=xr4[j]; xp[2*j]=v.x; xp[2*j+1]=v.y; }
      if(r2<21){
        const ulonglong2* kr2=(const ulonglong2*)(kbase + r2*22);
        #pragma unroll
        for(int j=0;j<11;j++){
          ulonglong2 wv=kr2[j];
          #pragma unroll
          for(int p=0;p<4;p++) fma2(accA[0][p], xp[p+j], wv.x);
          if(j<10){
            #pragma unroll
            for(int q=0;q<5;q++) fma2(accB[0][q], xp[q+j], wv.y);
          }
        }
      }
      if(r2>0){
        const ulonglong2* kr2=(const ulonglong2*)(kbase + (r2-1)*22);
        #pragma unroll
        for(int j=0;j<11;j++){
          ulonglong2 wv=kr2[j];
          #pragma unroll
          for(int p=0;p<4;p++) fma2(accA[1][p], xp[p+j], wv.x);
          if(j<10){
            #pragma unroll
            for(int q=0;q<5;q++) fma2(accB[1][q], xp[q+j], wv.y);
          }
        }
      }
    }
  }
  #pragma unroll
  for(int w2=0;w2<2;w2++){
    int y=y0+oy+w2;
    float* op=&g_out1[(b*256+y)*256+x0+tx];
    #pragma unroll
    for(int p=0;p<4;p++){
      float alo,ahi,blo,bhi,nlo,nhi;
      up2(accA[w2][p],alo,ahi); up2(accB[w2][p],blo,bhi); up2(accB[w2][p+1],nlo,nhi);
      op[2*p]=alo+bhi; op[2*p+1]=ahi+nlo;
    }
  }
}

// ---------------- ring helpers ----------------
__device__ __forceinline__ void ringpos(int rp,int&y,int&x){
  if(rp<256){y=0;x=rp;}
  else if(rp<512){y=255;x=rp-256;}
  else if(rp<766){y=rp-511;x=0;}
  else {y=rp-765;x=255;}
}

// ---------------- mega2: fused(6144, border-skip) + ring(1024) ----------------
__global__ __launch_bounds__(256) void k_mega2(const float* __restrict__ tr_b,
    const float* __restrict__ fu_w, const float* __restrict__ fu_b,
    float* __restrict__ out){
  extern __shared__ u64 smu[];
  int idx=blockIdx.x, t=threadIdx.x;
  if(idx<6144){
    // ---------- fused (interior only) ----------
    u64* s_wg2 = smu;                   // 3168
    u64* s_w52 = smu + 3168;            // 330
    float* s_xg = (float*)(smu + 3498); // 15552
    float* s_o1 = s_xg + 15552;         // 720
    float* s_cb = s_o1 + 720;           // 12
    int tile=idx&127, og=(idx>>7)%6, b=idx/768;
    int base=og*11;
    int y0=(tile>>3)*16, x0=(tile&7)*32;
    for(int i=t;i<15552;i+=256){
      int u=i/648, r=i%648, ly=r/36, lx=r%36;
      int gy=y0-1+ly, gx=x0-1+lx;
      float v=0.f;
      if(lx<34 && gy>=0&&gy<256&&gx>=0&&gx<256) v=g_xg[((b*24+u)*256+gy)*256+gx];
      s_xg[i]=v;
    }
    for(int i=t;i<720;i+=256){
      int ly=i/36, lx=i%36;
      int gy=y0-2+ly, gx=x0-2+lx;
      float v=0.f;
      if(gy>=0&&gy<256&&gx>=0&&gx<256) v=g_out1[(b*256+gy)*256+gx];
      s_o1[i]=v;
    }
    for(int i=t;i<3168;i+=256){
      int row=i/4, kx=i%4;
      int o=row/72, rr=row%72, u=rr/3, ky=rr%3;
      s_wg2[i] = (kx<3) ? g_fug2[((base+o)*24+u)*9+ky*3+kx] : 0ULL;
    }
    for(int i=t;i<330;i+=256){
      int row=i/6, kx=i%6;
      int o=row/5, ky=row%5;
      s_w52[i] = (kx<5) ? g_W52[(base+o)*25+ky*5+kx] : 0ULL;
    }
    if(t<11) s_cb[t]=g_cbias[base+t];
    __syncthreads();
    int quad=t>>6, tt=t&63;
    int ty=tt>>2, tx=(tt&3)*8;
    int yy=y0+ty, xxb=x0+tx;
    int obl=quad*3;
    if(obl+3>11) obl=8;
    u64 accA[3][4], accB[3][5];
    #pragma unroll
    for(int o=0;o<3;o++){
      #pragma unroll
      for(int p=0;p<4;p++) accA[o][p]=0ULL;
      #pragma unroll
      for(int q=0;q<5;q++) accB[o][q]=0ULL;
    }
    #pragma unroll 1
    for(int u=0;u<24;u++){
      const float* xb=s_xg+u*648;
      #pragma unroll
      for(int ky=0;ky<3;ky++){
        const ulonglong2* xr4=(const ulonglong2*)(xb+(ty+ky)*36+tx);
        u64 xp[6];
        #pragma unroll
        for(int j=0;j<3;j++){ ulonglong2 v=xr4[j]; xp[2*j]=v.x; xp[2*j+1]=v.y; }
        #pragma unroll
        for(int o=0;o<3;o++){
          const ulonglong2* wr2=(const ulonglong2*)(s_wg2 + (((obl+o)*24+u)*3+ky)*4);
          ulonglong2 w01=wr2[0], w2x=wr2[1];
          #pragma unroll
          for(int p=0;p<4;p++) fma2(accA[o][p], xp[p], w01.x);
          #pragma unroll
          for(int q=0;q<5;q++) fma2(accB[o][q], xp[q], w01.y);
          #pragma unroll
          for(int p=0;p<4;p++) fma2(accA[o][p], xp[p+1], w2x.x);
        }
      }
    }
    #pragma unroll
    for(int ky=0;ky<5;ky++){
      const ulonglong2* xr4=(const ulonglong2*)(s_o1+(ty+ky)*36+tx);
      u64 xp[6];
      #pragma unroll
      for(int j=0;j<3;j++){ ulonglong2 v=xr4[j]; xp[2*j]=v.x; xp[2*j+1]=v.y; }
      #pragma unroll
      for(int o=0;o<3;o++){
        const ulonglong2* wr2=(const ulonglong2*)(s_w52 + ((obl+o)*5+ky)*6);
        ulonglong2 w01=wr2[0], w23=wr2[1], w4x=wr2[2];
        #pragma unroll
        for(int p=0;p<4;p++) fma2(accA[o][p], xp[p],   w01.x);
        #pragma unroll
        for(int q=0;q<5;q++) fma2(accB[o][q], xp[q],   w01.y);
        #pragma unroll
        for(int p=0;p<4;p++) fma2(accA[o][p], xp[p+1], w23.x);
        #pragma unroll
        for(int q=0;q<5;q++) fma2(accB[o][q], xp[q+1], w23.y);
        #pragma unroll
        for(int p=0;p<4;p++) fma2(accA[o][p], xp[p+2], w4x.x);
      }
    }
    bool ybord = (yy==0)||(yy==255);
    #pragma unroll
    for(int o=0;o<3;o++){
      float cb=s_cb[obl+o];
      float* op=&out[((b*66+base+obl+o)*256+yy)*256+xxb];
      #pragma unroll
      for(int p=0;p<4;p++){
        float alo,ahi,blo,bhi,nlo,nhi;
        up2(accA[o][p],alo,ahi); up2(accB[o][p],blo,bhi); up2(accB[o][p+1],nlo,nhi);
        int gx=xxb+2*p;
        if(!ybord){
          if(gx!=0)     op[2*p]=cb+alo+bhi;
          if(gx+1!=255) op[2*p+1]=cb+ahi+nlo;
        }
      }
    }
  } else {
    // ---------- ring (exact border) ----------
    int i2=idx-6144;
    int chunk=i2&127, b=i2>>7;
    float* s_xaf=(float*)smu;     // 4752 floats
    for(int j=t;j<8*9*66;j+=256){
      int pi=j/594, r=j%594, tpos=r/66, m=r%66;
      int rp=chunk*8+pi;
      float v=0.f;
      if(rp<1020){
        int y,x; ringpos(rp,y,x);
        int p=y+tpos/3-1, q=x+tpos%3-1;
        if(p>=0&&p<256&&q>=0&&q<256){
          v=tr_b[m];
          #pragma unroll
          for(int tap=0;tap<9;tap++){
            int yy=p+tap/3-1, xx=q+tap%3-1;
            if(yy>=0&&yy<256&&xx>=0&&xx<256)
              v += g_treff[m*9+tap]*g_out1[(b*256+yy)*256+xx];
          }
        }
      }
      s_xaf[j]=v;
    }
    __syncthreads();
    for(int oi=t;oi<528;oi+=256){
      int o=oi>>3, pi=oi&7;
      int rp=chunk*8+pi;
      if(rp>=1020) continue;
      int y,x; ringpos(rp,y,x);
      float acc=fu_b[o];
      for(int u=0;u<24;u++){
        #pragma unroll
        for(int tap=0;tap<9;tap++){
          int yy=y+tap/3-1, xx=x+tap%3-1;
          if(yy>=0&&yy<256&&xx>=0&&xx<256)
            acc += g_fug[(o*24+u)*9+tap]*g_xg[((b*24+u)*256+yy)*256+xx];
        }
      }
      const float* sx = s_xaf + pi*594;
      for(int m=0;m<66;m++){
        const float* wr = fu_w + (o*132+66+m)*9;
        #pragma unroll
        for(int tap=0;tap<9;tap++) acc += wr[tap]*sx[tap*66+m];
      }
      out[((b*66+o)*256+y)*256+x]=acc;
    }
  }
}

// ---------------- launch ----------------
extern "C" void kernel_launch(void* const* d_in, const int* in_sizes, int n_in,
                              void* d_out, int out_size){
  const float* x    =(const float*)d_in[0];
  const float* wg   =(const float*)d_in[1];
  const float* p1_w =(const float*)d_in[2];
  const float* p1_b =(const float*)d_in[3];
  const float* p2_w =(const float*)d_in[4];
  const float* p3_w =(const float*)d_in[5];
  const float* cs_w =(const float*)d_in[6];
  const float* cs_b =(const float*)d_in[7];
  const float* tr_w =(const float*)d_in[8];
  const float* tr_b =(const float*)d_in[9];
  const float* fu_w =(const float*)d_in[10];
  const float* fu_b =(const float*)d_in[11];
  float* out=(float*)d_out;

  int smem_m1 = 14976*(int)sizeof(float) + 3168*(int)sizeof(u64);  // 85248
  int smem_dy = 3*36*148*(int)sizeof(float);                       // 63936
  int smem_m2 = 3498*(int)sizeof(u64) + (15552+720+12)*(int)sizeof(float); // 93120
  cudaFuncSetAttribute(k_mega1, cudaFuncAttributeMaxDynamicSharedMemorySize, smem_m1);
  cudaFuncSetAttribute(k_dyn,   cudaFuncAttributeMaxDynamicSharedMemorySize, smem_dy);
  cudaFuncSetAttribute(k_mega2, cudaFuncAttributeMaxDynamicSharedMemorySize, smem_m2);

  k_pre  <<<218,128>>>(tr_w,tr_b,fu_w,fu_b,wg,p1_w);
  k_mega1<<<7424,256,smem_m1>>>(x,p1_b,cs_w,cs_b,out);
  k_pred <<<8,512>>>(p2_w,p3_w);
  k_dyn  <<<dim3(32,8),128,smem_dy>>>(x);
  k_mega2<<<7168,256,smem_m2>>>(tr_b,fu_w,fu_b,out);
}

// round 15
// speedup vs baseline: 1.0018x; 1.0018x over previous
#include <cuda_runtime.h>

typedef unsigned long long u64;
#define FUSED_N 34603008  // 8*66*256*256

// ---------------- scratch (device globals; no allocations) ----------------
__device__ float g_xg[8*24*256*256];   // unique gauss channels
__device__ float g_out1[8*256*256];    // dynamic-conv output
__device__ float g_pool1p[8*128*9*2];  // pooled predictor stage 1 (2 half-partials)
__device__ u64   g_kern2[8*1323];      // predicted kernels, (w,w) pairs
__device__ float g_treff[66*9];
__device__ float g_fug[66*24*9];       // scalar (for ring)
__device__ u64   g_fug2[66*24*9];      // (w,w) pairs
__device__ float g_W5[66*25];
__device__ u64   g_W52[66*25];
__device__ float g_cbias[66];
__device__ int   g_bby[24*4];          // per-u: ky0, ky1, kxe(mult of 4), NJ
__device__ u64   g_wg2[24*441];        // gauss bank (w,w) pairs per unique u
__device__ u64   g_p1w2[128*363];      // p1 weights (w,w) pairs

__device__ __forceinline__ float leaky(float v){ return v>0.f ? v : 0.2f*v; }
__device__ __forceinline__ u64 pk2(float lo, float hi){
  u64 r; asm("mov.b64 %0, {%1,%2};" : "=l"(r) : "f"(lo), "f"(hi)); return r;
}
__device__ __forceinline__ void up2(u64 v, float&a, float&b){
  asm("mov.b64 {%0,%1}, %2;" : "=f"(a), "=f"(b) : "l"(v));
}
__device__ __forceinline__ void fma2(u64&d, u64 a, u64 b){
  asm("fma.rn.f32x2 %0, %1, %2, %0;" : "+l"(d) : "l"(a), "l"(b));
}

// ---------------- kernel 0: precompute effective weights (+ pair packing) ----------------
__global__ void k_pre(const float* __restrict__ tr_w, const float* __restrict__ tr_b,
                      const float* __restrict__ fu_w, const float* __restrict__ fu_b,
                      const float* __restrict__ w_gauss, const float* __restrict__ p1_w){
  __shared__ float s_tr[66*9];
  int t = threadIdx.x;
  for(int i=t;i<66*9;i+=blockDim.x){
    int m=i/9, tap=i%9;
    s_tr[i] = tr_w[(m*3+0)*9+tap]+tr_w[(m*3+1)*9+tap]+tr_w[(m*3+2)*9+tap];
  }
  __syncthreads();
  int blk = blockIdx.x;
  if(blk<66){
    int o=blk;
    if(t<9) g_treff[o*9+t]=s_tr[o*9+t];
    for(int i=t;i<24*9;i+=blockDim.x){
      int u=i/9, tap=i%9;
      float s=0.f;
      for(int c=0;c<66;c++) if(c/22 + c/3 == u) s += fu_w[(o*132+c)*9+tap];
      g_fug[(o*24+u)*9+tap]=s;
      g_fug2[(o*24+u)*9+tap]=pk2(s,s);
    }
    for(int i=t;i<25;i+=blockDim.x){
      int p=i/5,q=i%5;
      float s=0.f;
      for(int m=0;m<66;m++)
        for(int dy=0;dy<3;dy++){
          int ey=p-dy; if(ey<0||ey>2) continue;
          for(int dx=0;dx<3;dx++){
            int ex=q-dx; if(ex<0||ex>2) continue;
            s += fu_w[(o*132+66+m)*9+dy*3+dx]*s_tr[m*9+ey*3+ex];
          }
        }
      g_W5[o*25+i]=s;
      g_W52[o*25+i]=pk2(s,s);
    }
    if(t==0){
      float s=fu_b[o];
      for(int m=0;m<66;m++){
        float ws=0.f;
        for(int tap=0;tap<9;tap++) ws+=fu_w[(o*132+66+m)*9+tap];
        s += tr_b[m]*ws;
      }
      g_cbias[o]=s;
    }
  } else if(blk<90){
    int u=blk-66;
    int k = u - u/8;
    const float* wk = w_gauss + 3*k*441;
    for(int i=t;i<441;i+=blockDim.x){ float v=wk[i]; g_wg2[u*441+i]=pk2(v,v); }
    if(t==0){
      int y0=21,y1=-1,x0c=21,x1c=-1;
      for(int i=0;i<441;i++) if(wk[i]!=0.f){
        int y=i/21, xx=i%21;
        if(y<y0)y0=y; if(y>y1)y1=y;
        if(xx<x0c)x0c=xx; if(xx>x1c)x1c=xx;
      }
      if(y1<0){y0=10;y1=10;x0c=10;x1c=10;}
      int kxe = x0c & ~3;
      int nj  = (x1c - kxe)/2 + 1;
      g_bby[u*4]=y0; g_bby[u*4+1]=y1; g_bby[u*4+2]=kxe; g_bby[u*4+3]=nj;
    }
  } else {
    int o=blk-90;  // 0..127
    for(int i=t;i<363;i+=blockDim.x){ float v=p1_w[o*363+i]; g_p1w2[o*363+i]=pk2(v,v); }
  }
}

// ---------------- gauss inner body (templated col-window) ----------------
template<int NJ>
__device__ __forceinline__ void gauss_body(const float* s_x, const u64* s_w2,
    int ky0, int ky1, int oy, int tx, int kxe,
    u64 (&accA)[2][4], u64 (&accB)[2][5]){
  const int IW=148;
  const int NL = (NJ+5)/2;
  #pragma unroll 1
  for(int r2=ky0;r2<=ky1+1;r2++){
    const ulonglong2* xr4=(const ulonglong2*)(s_x + (oy+r2)*IW + tx + kxe);
    u64 xp[NL*2];
    #pragma unroll
    for(int l=0;l<NL;l++){ ulonglong2 v=xr4[l]; xp[2*l]=v.x; xp[2*l+1]=v.y; }
    if(r2<=ky1){
      const ulonglong2* kr2=(const ulonglong2*)(s_w2 + r2*22 + kxe);
      #pragma unroll
      for(int j=0;j<NJ;j++){
        ulonglong2 wv=kr2[j];
        #pragma unroll
        for(int p=0;p<4;p++) fma2(accA[0][p], xp[p+j], wv.x);
        #pragma unroll
        for(int q=0;q<5;q++) fma2(accB[0][q], xp[q+j], wv.y);
      }
    }
    if(r2>ky0){
      const ulonglong2* kr2=(const ulonglong2*)(s_w2 + (r2-1)*22 + kxe);
      #pragma unroll
      for(int j=0;j<NJ;j++){
        ulonglong2 wv=kr2[j];
        #pragma unroll
        for(int p=0;p<4;p++) fma2(accA[1][p], xp[p+j], wv.x);
        #pragma unroll
        for(int q=0;q<5;q++) fma2(accB[1][q], xp[q+j], wv.y);
      }
    }
  }
}

// ---------------- mega1: p1pool(2304) + gauss(3072) + ax(2048) in one launch ----------------
__global__ __launch_bounds__(256,2) void k_mega1(const float* __restrict__ x,
    const float* __restrict__ p1_b, const float* __restrict__ cs_w,
    const float* __restrict__ cs_b, float* __restrict__ out){
  extern __shared__ float sm[];
  __shared__ float s_acc[8];
  int idx=blockIdx.x;
  int t=threadIdx.x;
  if(idx<2304){
    // ---------- p1pool ----------
    float* s_x = sm;                 // 14976 floats
    u64* s_w2 = (u64*)(sm + 14976);  // 3168 u64
    int bin=idx%9, yb=(idx/9)%32, b=idx/288;
    int chunk=yb>>1, half=yb&1;
    int bi=bin/3, bj=bin%3;
    int hs=bi*250/3, ws=bj*250/3;
    const int bh=84, bw=84;
    int r0=half*42;
    for(int i=t;i<14976;i+=256){
      int c=i/4992, r=i%4992, ly=r/96, lx=r%96;
      int gy=hs+r0-2+ly, gx=ws-2+lx;
      float v=0.f;
      if(gy>=0&&gy<256&&gx>=0&&gx<256) v=x[((b*3+c)*256+gy)*256+gx];
      s_x[i]=v;
    }
    int ch0=chunk*8;
    for(int i=t;i<3168;i+=256){
      int row=i/12, kx=i%12;
      int cc=row/33, rr=row%33, c=rr/11, ky=rr%11;
      s_w2[i] = (kx<11) ? g_p1w2[(ch0+cc)*363 + c*121 + ky*11 + kx] : 0ULL;
    }
    if(t<8) s_acc[t]=0.f;
    __syncthreads();
    for(int task=t;task<1176;task+=256){
      int cc=task/147, r=task%147, pr=r/7, sg=r%7;
      int oy=2*pr, ox0=sg*12;
      u64 accA[2][6], accB[2][7];
      #pragma unroll
      for(int w2=0;w2<2;w2++){
        #pragma unroll
        for(int j=0;j<6;j++) accA[w2][j]=0ULL;
        #pragma unroll
        for(int j=0;j<7;j++) accB[w2][j]=0ULL;
      }
      #pragma unroll 1
      for(int c=0;c<3;c++){
        const float* xb = s_x + c*4992;
        const u64* wbase = s_w2 + (cc*3+c)*11*12;
        #pragma unroll 1
        for(int r2=0;r2<12;r2++){
          const ulonglong2* xr4=(const ulonglong2*)(xb + (oy+r2)*96 + ox0);
          u64 xp[12];
          #pragma unroll
          for(int j=0;j<6;j++){ ulonglong2 v=xr4[j]; xp[2*j]=v.x; xp[2*j+1]=v.y; }
          if(r2<11){
            const ulonglong2* wr2=(const ulonglong2*)(wbase + r2*12);
            #pragma unroll
            for(int j=0;j<6;j++){
              ulonglong2 wv=wr2[j];
              #pragma unroll
              for(int p=0;p<6;p++) fma2(accA[0][p], xp[p+j], wv.x);
              if(j<5){
                #pragma unroll
                for(int q=0;q<7;q++) fma2(accB[0][q], xp[q+j], wv.y);
              }
            }
          }
          if(r2>0){
            const ulonglong2* wr2=(const ulonglong2*)(wbase + (r2-1)*12);
            #pragma unroll
            for(int j=0;j<6;j++){
              ulonglong2 wv=wr2[j];
              #pragma unroll
              for(int p=0;p<6;p++) fma2(accA[1][p], xp[p+j], wv.x);
              if(j<5){
                #pragma unroll
                for(int q=0;q<7;q++) fma2(accB[1][q], xp[q+j], wv.y);
              }
            }
          }
        }
      }
      float bias=p1_b[ch0+cc];
      float ls=0.f;
      #pragma unroll
      for(int w2=0;w2<2;w2++){
        #pragma unroll
        for(int p=0;p<6;p++){
          float alo,ahi,blo,bhi,nlo,nhi;
          up2(accA[w2][p],alo,ahi);
          up2(accB[w2][p],blo,bhi);
          up2(accB[w2][p+1],nlo,nhi);
          ls+=leaky(alo+bhi+bias);
          ls+=leaky(ahi+nlo+bias);
        }
      }
      atomicAdd(&s_acc[cc], ls);
    }
    __syncthreads();
    if(t<8) g_pool1p[((b*128+ch0+t)*9+bin)*2+half]=s_acc[t]/(float)(bh*bw);
  } else if(idx<5376){
    // ---------- gauss ----------
    int i2=idx-2304;
    int tile=i2&15, u=(i2>>4)%24, b=i2/384;
    float* s_x = sm;                     // 7712 floats
    u64* s_w2 = (u64*)(sm + 7712);       // 462 u64
    const int IW=148;
    int y0=(tile>>1)*32, x0=(tile&1)*128;
    int g = u/8;
    for(int i=t;i<462;i+=256){
      int row=i/22, kx=i%22;
      s_w2[i] = (kx<21) ? g_wg2[u*441+row*21+kx] : 0ULL;
    }
    for(int i=t;i<52*148;i+=256){
      int ly=i/IW, lx=i%IW;
      int gy=y0-10+ly, gx=x0-10+lx;
      float v=0.f;
      if(gy>=0&&gy<256&&gx>=0&&gx<256) v=x[((b*3+g)*256+gy)*256+gx];
      s_x[i]=v;
    }
    if(t<16) s_x[52*148+t]=0.f;
    __syncthreads();
    int ky0=g_bby[u*4], ky1=g_bby[u*4+1], kxe=g_bby[u*4+2], nj=g_bby[u*4+3];
    int pr=t>>4, tx=(t&15)*8;
    int oy=2*pr;
    u64 accA[2][4], accB[2][5];
    #pragma unroll
    for(int w2=0;w2<2;w2++){
      #pragma unroll
      for(int j=0;j<4;j++) accA[w2][j]=0ULL;
      #pragma unroll
      for(int j=0;j<5;j++) accB[w2][j]=0ULL;
    }
    switch(nj){
      case 1:  gauss_body<1> (s_x,s_w2,ky0,ky1,oy,tx,kxe,accA,accB); break;
      case 2:  gauss_body<2> (s_x,s_w2,ky0,ky1,oy,tx,kxe,accA,accB); break;
      case 3:  gauss_body<3> (s_x,s_w2,ky0,ky1,oy,tx,kxe,accA,accB); break;
      case 4:  gauss_body<4> (s_x,s_w2,ky0,ky1,oy,tx,kxe,accA,accB); break;
      case 5:  gauss_body<5> (s_x,s_w2,ky0,ky1,oy,tx,kxe,accA,accB); break;
      case 6:  gauss_body<6> (s_x,s_w2,ky0,ky1,oy,tx,kxe,accA,accB); break;
      case 7:  gauss_body<7> (s_x,s_w2,ky0,ky1,oy,tx,kxe,accA,accB); break;
      case 8:  gauss_body<8> (s_x,s_w2,ky0,ky1,oy,tx,kxe,accA,accB); break;
      case 9:  gauss_body<9> (s_x,s_w2,ky0,ky1,oy,tx,kxe,accA,accB); break;
      case 10: gauss_body<10>(s_x,s_w2,ky0,ky1,oy,tx,kxe,accA,accB); break;
      default: gauss_body<11>(s_x,s_w2,ky0,ky1,oy,tx,kxe,accA,accB); break;
    }
    #pragma unroll
    for(int w2=0;w2<2;w2++){
      int y=y0+oy+w2;
      float* op=&g_xg[((b*24+u)*256+y)*256+x0+tx];
      #pragma unroll
      for(int p=0;p<4;p++){
        float alo,ahi,blo,bhi,nlo,nhi;
        up2(accA[w2][p],alo,ahi); up2(accB[w2][p],blo,bhi); up2(accB[w2][p+1],nlo,nhi);
        op[2*p]=alo+bhi; op[2*p+1]=ahi+nlo;
      }
    }
  } else {
    // ---------- ax ----------
    int i3=idx-5376;
    int b=i3/256, xb=i3%256;
    int p=xb*256+t;
    int y=p/256, xx=p%256;
    float acc[3]={cs_b[0],cs_b[1],cs_b[2]};
    #pragma unroll
    for(int ic=0;ic<3;ic++){
      #pragma unroll
      for(int ky=0;ky<3;ky++){
        int gy=y+ky-1; if(gy<0||gy>255) continue;
        #pragma unroll
        for(int kx=0;kx<3;kx++){
          int gx=xx+kx-1; if(gx<0||gx>255) continue;
          float v=x[((b*3+ic)*256+gy)*256+gx];
          #pragma unroll
          for(int o=0;o<3;o++) acc[o]+=v*cs_w[(o*3+ic)*9+ky*3+kx];
        }
      }
    }
    #pragma unroll
    for(int o=0;o<3;o++) out[FUSED_N + ((b*3+o)*256+y)*256+xx]=acc[o];
  }
}

// ---------------- kernel 2: predictor tail ----------------
__global__ void k_pred(const float* __restrict__ p2_w, const float* __restrict__ p3_w){
  int b = blockIdx.x;
  int t = threadIdx.x; // 512
  __shared__ float s_h1[128*9];
  __shared__ float s_h3[441*3];
  __shared__ float s_h4[441*3];
  __shared__ float s_red[3];
  for(int i=t;i<1152;i+=512)
    s_h1[i]=g_pool1p[(b*1152+i)*2]+g_pool1p[(b*1152+i)*2+1];
  __syncthreads();
  for(int j=t;j<441;j+=512){
    float acc[9];
    #pragma unroll
    for(int s=0;s<9;s++) acc[s]=0.f;
    const float* wr = p2_w + j*128;
    for(int i=0;i<128;i++){
      float w=wr[i];
      #pragma unroll
      for(int s=0;s<9;s++) acc[s]+=w*s_h1[i*9+s];
    }
    #pragma unroll
    for(int s=0;s<9;s++) acc[s]=leaky(acc[s]);
    #pragma unroll
    for(int r2=0;r2<3;r2++)
      s_h3[j*3+r2] = (acc[r2*3]+acc[r2*3+1]+acc[r2*3+2])*(1.f/3.f);
  }
  __syncthreads();
  for(int q=t;q<441;q+=512){
    float a0=0,a1=0,a2=0;
    const float* wr = p3_w + q*441;
    for(int j=0;j<441;j++){
      float w=wr[j];
      a0+=w*s_h3[j*3+0]; a1+=w*s_h3[j*3+1]; a2+=w*s_h3[j*3+2];
    }
    s_h4[q*3+0]=a0; s_h4[q*3+1]=a1; s_h4[q*3+2]=a2;
  }
  __syncthreads();
  if(t<3){
    float mx=-1e30f;
    for(int q=0;q<441;q++) mx=fmaxf(mx, s_h4[q*3+t]);
    s_red[t]=mx;
  }
  __syncthreads();
  for(int i=t;i<1323;i+=512) s_h4[i]=expf(s_h4[i]-s_red[i%3]);
  __syncthreads();
  if(t<3){
    float sm2=0.f;
    for(int q=0;q<441;q++) sm2+=s_h4[q*3+t];
    s_red[t]=1.f/sm2;
  }
  __syncthreads();
  for(int i=t;i<1323;i+=512){
    float v=s_h4[i]*s_red[i%3];
    g_kern2[b*1323+i]=pk2(v,v);
  }
}

// ---------------- kernel 3: dynamic conv (f32x2, 2-row x 8px, 16x128 tiles, 128 thr) ----------------
__global__ __launch_bounds__(128) void k_dyn(const float* __restrict__ x){
  extern __shared__ float s_x[];    // 3*36*148 = 15984 floats
  __shared__ __align__(16) u64 s_k2[3*21*22];
  const int IW=148, CH=36*148;
  int tile=blockIdx.x, b=blockIdx.y;
  int y0=(tile>>1)*16, x0=(tile&1)*128;
  int t=threadIdx.x; // 128
  for(int i=t;i<1386;i+=128){
    int row=i/22, kx=i%22;
    s_k2[i] = (kx<21) ? g_kern2[b*1323+row*21+kx] : 0ULL;
  }
  for(int i=t;i<3*CH;i+=128){
    int c=i/CH, r=i%CH, ly=r/IW, lx=r%IW;
    int gy=y0-10+ly, gx=x0-10+lx;
    float v=0.f;
    if(gy>=0&&gy<256&&gx>=0&&gx<256) v=x[((b*3+c)*256+gy)*256+gx];
    s_x[i]=v;
  }
  __syncthreads();
  int pr=t>>4, tx=(t&15)*8;
  int oy=2*pr;
  u64 accA[2][4], accB[2][5];
  #pragma unroll
  for(int w2=0;w2<2;w2++){
    #pragma unroll
    for(int j=0;j<4;j++) accA[w2][j]=0ULL;
    #pragma unroll
    for(int j=0;j<5;j++) accB[w2][j]=0ULL;
  }
  #pragma unroll 1
  for(int c=0;c<3;c++){
    const float* xb = s_x + c*CH;
    const u64* kbase = s_k2 + c*21*22;
    #pragma unroll 1
    for(int r2=0;r2<22;r2++){
      const ulonglong2* xr4=(const ulonglong2*)(xb + (oy+r2)*IW + tx);
      u64 xp[14];
      #pragma unroll
      for(int j=0;j<7;j++){ ulonglong2 v=xr4[j]; xp[2*j]=v.x; xp[2*j+1]=v.y; }
      if(r2<21){
        const ulonglong2* kr2=(const ulonglong2*)(kbase + r2*22);
        #pragma unroll
        for(int j=0;j<11;j++){
          ulonglong2 wv=kr2[j];
          #pragma unroll
          for(int p=0;p<4;p++) fma2(accA[0][p], xp[p+j], wv.x);
          if(j<10){
            #pragma unroll
            for(int q=0;q<5;q++) fma2(accB[0][q], xp[q+j], wv.y);
          }
        }
      }
      if(r2>0){
        const ulonglong2* kr2=(const ulonglong2*)(kbase + (r2-1)*22);
        #pragma unroll
        for(int j=0;j<11;j++){
          ulonglong2 wv=kr2[j];
          #pragma unroll
          for(int p=0;p<4;p++) fma2(accA[1][p], xp[p+j], wv.x);
          if(j<10){
            #pragma unroll
            for(int q=0;q<5;q++) fma2(accB[1][q], xp[q+j], wv.y);
          }
        }
      }
    }
  }
  #pragma unroll
  for(int w2=0;w2<2;w2++){
    int y=y0+oy+w2;
    float* op=&g_out1[(b*256+y)*256+x0+tx];
    #pragma unroll
    for(int p=0;p<4;p++){
      float alo,ahi,blo,bhi,nlo,nhi;
      up2(accA[w2][p],alo,ahi); up2(accB[w2][p],blo,bhi); up2(accB[w2][p+1],nlo,nhi);
      op[2*p]=alo+bhi; op[2*p+1]=ahi+nlo;
    }
  }
}

// ---------------- ring helpers ----------------
__device__ __forceinline__ void ringpos(int rp,int&y,int&x){
  if(rp<256){y=0;x=rp;}
  else if(rp<512){y=255;x=rp-256;}
  else if(rp<766){y=rp-511;x=0;}
  else {y=rp-765;x=255;}
}

// ---------------- mega2: fused(6144, border-skip) + ring(1024) ----------------
__global__ __launch_bounds__(256) void k_mega2(const float* __restrict__ tr_b,
    const float* __restrict__ fu_w, const float* __restrict__ fu_b,
    float* __restrict__ out){
  extern __shared__ u64 smu[];
  int idx=blockIdx.x, t=threadIdx.x;
  if(idx<6144){
    // ---------- fused (interior only) ----------
    u64* s_wg2 = smu;                   // 3168
    u64* s_w52 = smu + 3168;            // 330
    float* s_xg = (float*)(smu + 3498); // 15552
    float* s_o1 = s_xg + 15552;         // 720
    float* s_cb = s_o1 + 720;           // 12
    int tile=idx&127, og=(idx>>7)%6, b=idx/768;
    int base=og*11;
    int y0=(tile>>3)*16, x0=(tile&7)*32;
    for(int i=t;i<15552;i+=256){
      int u=i/648, r=i%648, ly=r/36, lx=r%36;
      int gy=y0-1+ly, gx=x0-1+lx;
      float v=0.f;
      if(lx<34 && gy>=0&&gy<256&&gx>=0&&gx<256) v=g_xg[((b*24+u)*256+gy)*256+gx];
      s_xg[i]=v;
    }
    for(int i=t;i<720;i+=256){
      int ly=i/36, lx=i%36;
      int gy=y0-2+ly, gx=x0-2+lx;
      float v=0.f;
      if(gy>=0&&gy<256&&gx>=0&&gx<256) v=g_out1[(b*256+gy)*256+gx];
      s_o1[i]=v;
    }
    for(int i=t;i<3168;i+=256){
      int row=i/4, kx=i%4;
      int o=row/72, rr=row%72, u=rr/3, ky=rr%3;
      s_wg2[i] = (kx<3) ? g_fug2[((base+o)*24+u)*9+ky*3+kx] : 0ULL;
    }
    for(int i=t;i<330;i+=256){
      int row=i/6, kx=i%6;
      int o=row/5, ky=row%5;
      s_w52[i] = (kx<5) ? g_W52[(base+o)*25+ky*5+kx] : 0ULL;
    }
    if(t<11) s_cb[t]=g_cbias[base+t];
    __syncthreads();
    int quad=t>>6, tt=t&63;
    int ty=tt>>2, tx=(tt&3)*8;
    int yy=y0+ty, xxb=x0+tx;
    int obl=quad*3;
    if(obl+3>11) obl=8;
    u64 accA[3][4], accB[3][5];
    #pragma unroll
    for(int o=0;o<3;o++){
      #pragma unroll
      for(int p=0;p<4;p++) accA[o][p]=0ULL;
      #pragma unroll
      for(int q=0;q<5;q++) accB[o][q]=0ULL;
    }
    #pragma unroll 1
    for(int u=0;u<24;u++){
      const float* xb=s_xg+u*648;
      #pragma unroll
      for(int ky=0;ky<3;ky++){
        const ulonglong2* xr4=(const ulonglong2*)(xb+(ty+ky)*36+tx);
        u64 xp[6];
        #pragma unroll
        for(int j=0;j<3;j++){ ulonglong2 v=xr4[j]; xp[2*j]=v.x; xp[2*j+1]=v.y; }
        #pragma unroll
        for(int o=0;o<3;o++){
          const ulonglong2* wr2=(const ulonglong2*)(s_wg2 + (((obl+o)*24+u)*3+ky)*4);
          ulonglong2 w01=wr2[0], w2x=wr2[1];
          #pragma unroll
          for(int p=0;p<4;p++) fma2(accA[o][p], xp[p], w01.x);
          #pragma unroll
          for(int q=0;q<5;q++) fma2(accB[o][q], xp[q], w01.y);
          #pragma unroll
          for(int p=0;p<4;p++) fma2(accA[o][p], xp[p+1], w2x.x);
        }
      }
    }
    #pragma unroll
    for(int ky=0;ky<5;ky++){
      const ulonglong2* xr4=(const ulonglong2*)(s_o1+(ty+ky)*36+tx);
      u64 xp[6];
      #pragma unroll
      for(int j=0;j<3;j++){ ulonglong2 v=xr4[j]; xp[2*j]=v.x; xp[2*j+1]=v.y; }
      #pragma unroll
      for(int o=0;o<3;o++){
        const ulonglong2* wr2=(const ulonglong2*)(s_w52 + ((obl+o)*5+ky)*6);
        ulonglong2 w01=wr2[0], w23=wr2[1], w4x=wr2[2];
        #pragma unroll
        for(int p=0;p<4;p++) fma2(accA[o][p], xp[p],   w01.x);
        #pragma unroll
        for(int q=0;q<5;q++) fma2(accB[o][q], xp[q],   w01.y);
        #pragma unroll
        for(int p=0;p<4;p++) fma2(accA[o][p], xp[p+1], w23.x);
        #pragma unroll
        for(int q=0;q<5;q++) fma2(accB[o][q], xp[q+1], w23.y);
        #pragma unroll
        for(int p=0;p<4;p++) fma2(accA[o][p], xp[p+2], w4x.x);
      }
    }
    bool ybord = (yy==0)||(yy==255);
    #pragma unroll
    for(int o=0;o<3;o++){
      float cb=s_cb[obl+o];
      float* op=&out[((b*66+base+obl+o)*256+yy)*256+xxb];
      #pragma unroll
      for(int p=0;p<4;p++){
        float alo,ahi,blo,bhi,nlo,nhi;
        up2(accA[o][p],alo,ahi); up2(accB[o][p],blo,bhi); up2(accB[o][p+1],nlo,nhi);
        int gx=xxb+2*p;
        if(!ybord){
          if(gx!=0)     op[2*p]=cb+alo+bhi;
          if(gx+1!=255) op[2*p+1]=cb+ahi+nlo;
        }
      }
    }
  } else {
    // ---------- ring (exact border) ----------
    int i2=idx-6144;
    int chunk=i2&127, b=i2>>7;
    float* s_xaf=(float*)smu;     // 4752 floats
    for(int j=t;j<8*9*66;j+=256){
      int pi=j/594, r=j%594, tpos=r/66, m=r%66;
      int rp=chunk*8+pi;
      float v=0.f;
      if(rp<1020){
        int y,x; ringpos(rp,y,x);
        int p=y+tpos/3-1, q=x+tpos%3-1;
        if(p>=0&&p<256&&q>=0&&q<256){
          v=tr_b[m];
          #pragma unroll
          for(int tap=0;tap<9;tap++){
            int yy=p+tap/3-1, xx=q+tap%3-1;
            if(yy>=0&&yy<256&&xx>=0&&xx<256)
              v += g_treff[m*9+tap]*g_out1[(b*256+yy)*256+xx];
          }
        }
      }
      s_xaf[j]=v;
    }
    __syncthreads();
    for(int oi=t;oi<528;oi+=256){
      int o=oi>>3, pi=oi&7;
      int rp=chunk*8+pi;
      if(rp>=1020) continue;
      int y,x; ringpos(rp,y,x);
      float acc=fu_b[o];
      for(int u=0;u<24;u++){
        #pragma unroll
        for(int tap=0;tap<9;tap++){
          int yy=y+tap/3-1, xx=x+tap%3-1;
          if(yy>=0&&yy<256&&xx>=0&&xx<256)
            acc += g_fug[(o*24+u)*9+tap]*g_xg[((b*24+u)*256+yy)*256+xx];
        }
      }
      const float* sx = s_xaf + pi*594;
      for(int m=0;m<66;m++){
        const float* wr = fu_w + (o*132+66+m)*9;
        #pragma unroll
        for(int tap=0;tap<9;tap++) acc += wr[tap]*sx[tap*66+m];
      }
      out[((b*66+o)*256+y)*256+x]=acc;
    }
  }
}

// ---------------- launch ----------------
extern "C" void kernel_launch(void* const* d_in, const int* in_sizes, int n_in,
                              void* d_out, int out_size){
  const float* x    =(const float*)d_in[0];
  const float* wg   =(const float*)d_in[1];
  const float* p1_w =(const float*)d_in[2];
  const float* p1_b =(const float*)d_in[3];
  const float* p2_w =(const float*)d_in[4];
  const float* p3_w =(const float*)d_in[5];
  const float* cs_w =(const float*)d_in[6];
  const float* cs_b =(const float*)d_in[7];
  const float* tr_w =(const float*)d_in[8];
  const float* tr_b =(const float*)d_in[9];
  const float* fu_w =(const float*)d_in[10];
  const float* fu_b =(const float*)d_in[11];
  float* out=(float*)d_out;

  int smem_m1 = 14976*(int)sizeof(float) + 3168*(int)sizeof(u64);  // 85248
  int smem_dy = 3*36*148*(int)sizeof(float);                       // 63936
  int smem_m2 = 3498*(int)sizeof(u64) + (15552+720+12)*(int)sizeof(float); // 93120
  cudaFuncSetAttribute(k_mega1, cudaFuncAttributeMaxDynamicSharedMemorySize, smem_m1);
  cudaFuncSetAttribute(k_dyn,   cudaFuncAttributeMaxDynamicSharedMemorySize, smem_dy);
  cudaFuncSetAttribute(k_mega2, cudaFuncAttributeMaxDynamicSharedMemorySize, smem_m2);

  k_pre  <<<218,128>>>(tr_w,tr_b,fu_w,fu_b,wg,p1_w);
  k_mega1<<<7424,256,smem_m1>>>(x,p1_b,cs_w,cs_b,out);
  k_pred <<<8,512>>>(p2_w,p3_w);
  k_dyn  <<<dim3(32,8),128,smem_dy>>>(x);
  k_mega2<<<7168,256,smem_m2>>>(tr_b,fu_w,fu_b,out);
}